// round 1
// baseline (speedup 1.0000x reference)
#include <cuda_runtime.h>

#define BATCH 4
#define NPTS  8192
#define KNN   8
#define TILE  2048
#define QBLK  256

// Precomputed candidate/query arrays: xyz + squared-norm in .w
__device__ float4 g_pred4[BATCH * NPTS];
__device__ float4 g_targ4[BATCH * NPTS];

__global__ void prep_kernel(const float* __restrict__ src,
                            const float* __restrict__ tgt,
                            const float* __restrict__ flow) {
    int i = blockIdx.x * blockDim.x + threadIdx.x;
    if (i >= BATCH * NPTS) return;
    float sx = src[3 * i + 0], sy = src[3 * i + 1], sz = src[3 * i + 2];
    float fx = flow[3 * i + 0], fy = flow[3 * i + 1], fz = flow[3 * i + 2];
    float px = sx + fx, py = sy + fy, pz = sz + fz;
    g_pred4[i] = make_float4(px, py, pz, px * px + py * py + pz * pz);
    float tx = tgt[3 * i + 0], ty = tgt[3 * i + 1], tz = tgt[3 * i + 2];
    g_targ4[i] = make_float4(tx, ty, tz, tx * tx + ty * ty + tz * tz);
}

__global__ void __launch_bounds__(QBLK)
chamfer_kernel(float* __restrict__ out) {
    __shared__ float4 sm[TILE];
    __shared__ float red[QBLK];

    const int b   = blockIdx.y;
    const int dir = blockIdx.z;
    const float4* q4 = (dir == 0 ? g_pred4 : g_targ4) + b * NPTS;
    const float4* c4 = (dir == 0 ? g_targ4 : g_pred4) + b * NPTS;

    const int qi = blockIdx.x * QBLK + threadIdx.x;
    const float4 q = q4[qi];
    const float ax = -2.0f * q.x;
    const float ay = -2.0f * q.y;
    const float az = -2.0f * q.z;

    // Sorted descending: h[0] = current 8th-smallest (largest kept value)
    float h[KNN];
#pragma unroll
    for (int i = 0; i < KNN; ++i) h[i] = 3.0e38f;

    for (int t0 = 0; t0 < NPTS; t0 += TILE) {
        __syncthreads();
#pragma unroll
        for (int l = 0; l < TILE / QBLK; ++l)
            sm[threadIdx.x + l * QBLK] = c4[t0 + threadIdx.x + l * QBLK];
        __syncthreads();

#pragma unroll 8
        for (int j = 0; j < TILE; ++j) {
            float4 c = sm[j];  // broadcast LDS.128 (uniform j across warp)
            // t = |p|^2 - 2 q.p  (= d2 - |q|^2; |q|^2 is a per-query constant)
            float t = fmaf(ax, c.x, fmaf(ay, c.y, fmaf(az, c.z, c.w)));
            if (t < h[0]) {
                // branchless insert into sorted-descending 8-list
                float v = t;
#pragma unroll
                for (int i = 0; i < KNN - 1; ++i) {
                    float nx = h[i + 1];
                    h[i] = fmaxf(v, nx);
                    v = fminf(v, nx);
                }
                h[KNN - 1] = v;
            }
        }
    }

    float s = 0.0f;
#pragma unroll
    for (int i = 0; i < KNN; ++i) {
        float d2 = fmaxf(q.w + h[i], 0.0f);  // re-add |q|^2, clamp rounding
        s += sqrtf(d2);
    }

    red[threadIdx.x] = s;
    __syncthreads();
#pragma unroll
    for (int off = QBLK / 2; off > 0; off >>= 1) {
        if (threadIdx.x < off) red[threadIdx.x] += red[threadIdx.x + off];
        __syncthreads();
    }
    if (threadIdx.x == 0) {
        // loss = sum(sqrt d) / (K * B * N)  over both directions
        atomicAdd(out, red[0] * (1.0f / (KNN * BATCH * NPTS)));
    }
}

extern "C" void kernel_launch(void* const* d_in, const int* in_sizes, int n_in,
                              void* d_out, int out_size) {
    const float* src  = (const float*)d_in[0];  // pc_source [4,8192,3]
    const float* tgt  = (const float*)d_in[1];  // pc_target [4,8192,3]
    const float* flow = (const float*)d_in[2];  // pred_flow [4,8192,3]
    float* out = (float*)d_out;

    cudaMemsetAsync(out, 0, sizeof(float), 0);

    int npts = BATCH * NPTS;
    prep_kernel<<<(npts + 255) / 256, 256>>>(src, tgt, flow);

    dim3 grid(NPTS / QBLK, BATCH, 2);
    chamfer_kernel<<<grid, QBLK>>>(out);
}

// round 2
// speedup vs baseline: 1.8058x; 1.8058x over previous
#include <cuda_runtime.h>

#define BATCH 4
#define NPTS  8192
#define KNN   8
#define TILE  2048
#define QBLK  128

typedef unsigned long long u64;

// Query arrays (AoS float4: xyz + |p|^2) — one read per thread
__device__ float4 g_pred4[BATCH * NPTS];
__device__ float4 g_targ4[BATCH * NPTS];
// Candidate arrays, SoA, set 0 = pred, set 1 = targ
__device__ float g_sx[2 * BATCH * NPTS];
__device__ float g_sy[2 * BATCH * NPTS];
__device__ float g_sz[2 * BATCH * NPTS];
__device__ float g_sw[2 * BATCH * NPTS];

__device__ __forceinline__ u64 pack2(float lo, float hi) {
    u64 r;
    asm("mov.b64 %0, {%1, %2};" : "=l"(r) : "f"(lo), "f"(hi));
    return r;
}
__device__ __forceinline__ float lo32(u64 v) { return __uint_as_float((unsigned)v); }
__device__ __forceinline__ float hi32(u64 v) { return __uint_as_float((unsigned)(v >> 32)); }

__device__ __forceinline__ u64 ffma2(u64 a, u64 b, u64 c) {
    u64 d;
    asm("fma.rn.f32x2 %0, %1, %2, %3;" : "=l"(d) : "l"(a), "l"(b), "l"(c));
    return d;
}
__device__ __forceinline__ u64 fadd2(u64 a, u64 b) {
    u64 d;
    asm("add.rn.f32x2 %0, %1, %2;" : "=l"(d) : "l"(a), "l"(b));
    return d;
}

__global__ void prep_kernel(const float* __restrict__ src,
                            const float* __restrict__ tgt,
                            const float* __restrict__ flow) {
    int i = blockIdx.x * blockDim.x + threadIdx.x;
    if (i >= BATCH * NPTS) return;
    float px = src[3 * i + 0] + flow[3 * i + 0];
    float py = src[3 * i + 1] + flow[3 * i + 1];
    float pz = src[3 * i + 2] + flow[3 * i + 2];
    float pw = px * px + py * py + pz * pz;
    g_pred4[i] = make_float4(px, py, pz, pw);
    g_sx[i] = px; g_sy[i] = py; g_sz[i] = pz; g_sw[i] = pw;

    float tx = tgt[3 * i + 0], ty = tgt[3 * i + 1], tz = tgt[3 * i + 2];
    float tw = tx * tx + ty * ty + tz * tz;
    g_targ4[i] = make_float4(tx, ty, tz, tw);
    int j = BATCH * NPTS + i;
    g_sx[j] = tx; g_sy[j] = ty; g_sz[j] = tz; g_sw[j] = tw;
}

// Branchless sorted-descending insert (v must satisfy v < h[0] on entry)
#define INSERT8(h, val)                          \
    do {                                         \
        float _v = (val);                        \
        _Pragma("unroll")                        \
        for (int _i = 0; _i < KNN - 1; ++_i) {   \
            float _nx = h[_i + 1];               \
            h[_i] = fmaxf(_v, _nx);              \
            _v = fminf(_v, _nx);                 \
        }                                        \
        h[KNN - 1] = _v;                         \
    } while (0)

__global__ void __launch_bounds__(QBLK)
chamfer_kernel(float* __restrict__ out) {
    __shared__ __align__(16) float sx[TILE];
    __shared__ __align__(16) float sy[TILE];
    __shared__ __align__(16) float sz[TILE];
    __shared__ __align__(16) float sw[TILE];
    __shared__ float red[QBLK];

    const int b   = blockIdx.y;
    const int dir = blockIdx.z;
    const float4* q4 = (dir == 0 ? g_pred4 : g_targ4) + b * NPTS;
    const int coff = (dir == 0 ? 1 : 0) * BATCH * NPTS + b * NPTS;
    const float* cx = g_sx + coff;
    const float* cy = g_sy + coff;
    const float* cz = g_sz + coff;
    const float* cw = g_sw + coff;

    const int qi = blockIdx.x * QBLK + threadIdx.x;
    const float4 q = q4[qi];
    const u64 ax2 = pack2(-2.0f * q.x, -2.0f * q.x);
    const u64 ay2 = pack2(-2.0f * q.y, -2.0f * q.y);
    const u64 az2 = pack2(-2.0f * q.z, -2.0f * q.z);

    float h[KNN];
#pragma unroll
    for (int i = 0; i < KNN; ++i) h[i] = 1.0e30f;
    u64 nh2 = pack2(-1.0e30f, -1.0e30f);  // packed (-h[0], -h[0])

    for (int t0 = 0; t0 < NPTS; t0 += TILE) {
        __syncthreads();
#pragma unroll
        for (int l = threadIdx.x; l < TILE / 4; l += QBLK) {
            ((float4*)sx)[l] = ((const float4*)(cx + t0))[l];
            ((float4*)sy)[l] = ((const float4*)(cy + t0))[l];
            ((float4*)sz)[l] = ((const float4*)(cz + t0))[l];
            ((float4*)sw)[l] = ((const float4*)(cw + t0))[l];
        }
        __syncthreads();

#pragma unroll 4
        for (int j = 0; j < TILE; j += 4) {
            // 4 candidates: one LDS.128 per coordinate array (broadcast)
            const ulonglong2 X = *(const ulonglong2*)(sx + j);
            const ulonglong2 Y = *(const ulonglong2*)(sy + j);
            const ulonglong2 Z = *(const ulonglong2*)(sz + j);
            const ulonglong2 W = *(const ulonglong2*)(sw + j);
            // t = |c|^2 - 2 q.c   (two candidates per packed op)
            u64 t01 = ffma2(ax2, X.x, ffma2(ay2, Y.x, ffma2(az2, Z.x, W.x)));
            u64 t23 = ffma2(ax2, X.y, ffma2(ay2, Y.y, ffma2(az2, Z.y, W.y)));
            // sign test: any (t_i - h0) < 0 ?
            u64 r = fadd2(t01, nh2) | fadd2(t23, nh2);
            if (((unsigned)(r >> 32) | (unsigned)r) & 0x80000000u) {
                float t0v = lo32(t01), t1v = hi32(t01);
                float t2v = lo32(t23), t3v = hi32(t23);
                if (t0v < h[0]) INSERT8(h, t0v);
                if (t1v < h[0]) INSERT8(h, t1v);
                if (t2v < h[0]) INSERT8(h, t2v);
                if (t3v < h[0]) INSERT8(h, t3v);
                nh2 = pack2(-h[0], -h[0]);
            }
        }
    }

    float s = 0.0f;
#pragma unroll
    for (int i = 0; i < KNN; ++i)
        s += sqrtf(fmaxf(q.w + h[i], 0.0f));

    red[threadIdx.x] = s;
    __syncthreads();
#pragma unroll
    for (int off = QBLK / 2; off > 0; off >>= 1) {
        if (threadIdx.x < off) red[threadIdx.x] += red[threadIdx.x + off];
        __syncthreads();
    }
    if (threadIdx.x == 0)
        atomicAdd(out, red[0] * (1.0f / (KNN * BATCH * NPTS)));
}

extern "C" void kernel_launch(void* const* d_in, const int* in_sizes, int n_in,
                              void* d_out, int out_size) {
    const float* src  = (const float*)d_in[0];
    const float* tgt  = (const float*)d_in[1];
    const float* flow = (const float*)d_in[2];
    float* out = (float*)d_out;

    cudaMemsetAsync(out, 0, sizeof(float), 0);

    int npts = BATCH * NPTS;
    prep_kernel<<<(npts + 255) / 256, 256>>>(src, tgt, flow);

    dim3 grid(NPTS / QBLK, BATCH, 2);
    chamfer_kernel<<<grid, QBLK>>>(out);
}

// round 3
// speedup vs baseline: 1.8513x; 1.0252x over previous
#include <cuda_runtime.h>

#define BATCH   4
#define NPTS    8192
#define KNN     8
#define TILE    2048
#define QBLK    128      // queries per block
#define THREADS 256      // 2 threads per query (candidate split)

typedef unsigned long long u64;

__device__ float4 g_pred4[BATCH * NPTS];
__device__ float4 g_targ4[BATCH * NPTS];
__device__ float g_sx[2 * BATCH * NPTS];
__device__ float g_sy[2 * BATCH * NPTS];
__device__ float g_sz[2 * BATCH * NPTS];
__device__ float g_sw[2 * BATCH * NPTS];

__device__ __forceinline__ u64 pack2(float lo, float hi) {
    u64 r;
    asm("mov.b64 %0, {%1, %2};" : "=l"(r) : "f"(lo), "f"(hi));
    return r;
}
__device__ __forceinline__ float lo32(u64 v) { return __uint_as_float((unsigned)v); }
__device__ __forceinline__ float hi32(u64 v) { return __uint_as_float((unsigned)(v >> 32)); }
__device__ __forceinline__ u64 ffma2(u64 a, u64 b, u64 c) {
    u64 d;
    asm("fma.rn.f32x2 %0, %1, %2, %3;" : "=l"(d) : "l"(a), "l"(b), "l"(c));
    return d;
}

__global__ void prep_kernel(const float* __restrict__ src,
                            const float* __restrict__ tgt,
                            const float* __restrict__ flow) {
    int i = blockIdx.x * blockDim.x + threadIdx.x;
    if (i >= BATCH * NPTS) return;
    float px = src[3 * i + 0] + flow[3 * i + 0];
    float py = src[3 * i + 1] + flow[3 * i + 1];
    float pz = src[3 * i + 2] + flow[3 * i + 2];
    float pw = px * px + py * py + pz * pz;
    g_pred4[i] = make_float4(px, py, pz, pw);
    g_sx[i] = px; g_sy[i] = py; g_sz[i] = pz; g_sw[i] = pw;

    float tx = tgt[3 * i + 0], ty = tgt[3 * i + 1], tz = tgt[3 * i + 2];
    float tw = tx * tx + ty * ty + tz * tz;
    g_targ4[i] = make_float4(tx, ty, tz, tw);
    int j = BATCH * NPTS + i;
    g_sx[j] = tx; g_sy[j] = ty; g_sz[j] = tz; g_sw[j] = tw;
}

// Branchless sorted-descending insert (caller guarantees val < h[0])
#define INSERT8(h, val)                          \
    do {                                         \
        float _v = (val);                        \
        _Pragma("unroll")                        \
        for (int _i = 0; _i < KNN - 1; ++_i) {   \
            float _nx = h[_i + 1];               \
            h[_i] = fmaxf(_v, _nx);              \
            _v = fminf(_v, _nx);                 \
        }                                        \
        h[KNN - 1] = _v;                         \
    } while (0)

#define TRYINS(h, val) do { if ((val) < h[0]) INSERT8(h, (val)); } while (0)

__global__ void __launch_bounds__(THREADS, 4)
chamfer_kernel(float* __restrict__ out) {
    __shared__ __align__(16) float sx[TILE];
    __shared__ __align__(16) float sy[TILE];
    __shared__ __align__(16) float sz[TILE];
    __shared__ __align__(16) float sw[TILE];
    __shared__ float m8[QBLK][KNN];
    __shared__ float red[QBLK];

    const int b   = blockIdx.y;
    const int dir = blockIdx.z;
    const float4* q4 = (dir == 0 ? g_pred4 : g_targ4) + b * NPTS;
    const int coff = (dir == 0 ? 1 : 0) * BATCH * NPTS + b * NPTS;
    const float* cx = g_sx + coff;
    const float* cy = g_sy + coff;
    const float* cz = g_sz + coff;
    const float* cw = g_sw + coff;

    const int qt   = threadIdx.x & (QBLK - 1);
    const int half = threadIdx.x >> 7;       // warp-uniform
    const int qi   = blockIdx.x * QBLK + qt;
    const float4 q = q4[qi];
    const u64 ax2 = pack2(-2.0f * q.x, -2.0f * q.x);
    const u64 ay2 = pack2(-2.0f * q.y, -2.0f * q.y);
    const u64 az2 = pack2(-2.0f * q.z, -2.0f * q.z);

    float h[KNN];
#pragma unroll
    for (int i = 0; i < KNN; ++i) h[i] = 1.0e30f;

    const int jo = half * 8;                 // interleaved 8-candidate groups

    for (int t0 = 0; t0 < NPTS; t0 += TILE) {
        __syncthreads();
#pragma unroll
        for (int l = threadIdx.x; l < TILE / 4; l += THREADS) {
            ((float4*)sx)[l] = ((const float4*)(cx + t0))[l];
            ((float4*)sy)[l] = ((const float4*)(cy + t0))[l];
            ((float4*)sz)[l] = ((const float4*)(cz + t0))[l];
            ((float4*)sw)[l] = ((const float4*)(cw + t0))[l];
        }
        __syncthreads();

#pragma unroll 2
        for (int j = 0; j < TILE; j += 16) {
            const float* bx = sx + j + jo;
            const float* by = sy + j + jo;
            const float* bz = sz + j + jo;
            const float* bw = sw + j + jo;
            const ulonglong2 X0 = ((const ulonglong2*)bx)[0];
            const ulonglong2 X1 = ((const ulonglong2*)bx)[1];
            const ulonglong2 Y0 = ((const ulonglong2*)by)[0];
            const ulonglong2 Y1 = ((const ulonglong2*)by)[1];
            const ulonglong2 Z0 = ((const ulonglong2*)bz)[0];
            const ulonglong2 Z1 = ((const ulonglong2*)bz)[1];
            const ulonglong2 W0 = ((const ulonglong2*)bw)[0];
            const ulonglong2 W1 = ((const ulonglong2*)bw)[1];

            // t = |c|^2 - 2 q.c  (ranking key; |q|^2 re-added at the end)
            u64 t01 = ffma2(ax2, X0.x, ffma2(ay2, Y0.x, ffma2(az2, Z0.x, W0.x)));
            u64 t23 = ffma2(ax2, X0.y, ffma2(ay2, Y0.y, ffma2(az2, Z0.y, W0.y)));
            u64 t45 = ffma2(ax2, X1.x, ffma2(ay2, Y1.x, ffma2(az2, Z1.x, W1.x)));
            u64 t67 = ffma2(ax2, X1.y, ffma2(ay2, Y1.y, ffma2(az2, Z1.y, W1.y)));

            float f0 = lo32(t01), f1 = hi32(t01);
            float f2 = lo32(t23), f3 = hi32(t23);
            float f4 = lo32(t45), f5 = hi32(t45);
            float f6 = lo32(t67), f7 = hi32(t67);

            // FMNMX min-tree over the 8 candidates, single guard branch
            float m = fminf(fminf(fminf(f0, f1), fminf(f2, f3)),
                            fminf(fminf(f4, f5), fminf(f6, f7)));
            if (m < h[0]) {
                TRYINS(h, f0); TRYINS(h, f1);
                TRYINS(h, f2); TRYINS(h, f3);
                TRYINS(h, f4); TRYINS(h, f5);
                TRYINS(h, f6); TRYINS(h, f7);
            }
        }
    }

    // Merge the two halves' top-8 lists
    if (half) {
#pragma unroll
        for (int i = 0; i < KNN; ++i) m8[qt][i] = h[i];
    }
    __syncthreads();
    if (!half) {
#pragma unroll
        for (int i = 0; i < KNN; ++i) {
            float v = m8[qt][i];
            TRYINS(h, v);
        }
        float s = 0.0f;
#pragma unroll
        for (int i = 0; i < KNN; ++i)
            s += sqrtf(fmaxf(q.w + h[i], 0.0f));
        red[qt] = s;
    }
    __syncthreads();
#pragma unroll
    for (int off = QBLK / 2; off > 0; off >>= 1) {
        if (threadIdx.x < off) red[threadIdx.x] += red[threadIdx.x + off];
        __syncthreads();
    }
    if (threadIdx.x == 0)
        atomicAdd(out, red[0] * (1.0f / (KNN * BATCH * NPTS)));
}

extern "C" void kernel_launch(void* const* d_in, const int* in_sizes, int n_in,
                              void* d_out, int out_size) {
    const float* src  = (const float*)d_in[0];
    const float* tgt  = (const float*)d_in[1];
    const float* flow = (const float*)d_in[2];
    float* out = (float*)d_out;

    cudaMemsetAsync(out, 0, sizeof(float), 0);

    int npts = BATCH * NPTS;
    prep_kernel<<<(npts + 255) / 256, 256>>>(src, tgt, flow);

    dim3 grid(NPTS / QBLK, BATCH, 2);
    chamfer_kernel<<<grid, THREADS>>>(out);
}

// round 7
// speedup vs baseline: 2.0920x; 1.1300x over previous
#include <cuda_runtime.h>

#define BATCH   4
#define NPTS    8192
#define KNN     8
#define TILE    1024
#define QBLK    64       // queries per block
#define THREADS 128      // 2 threads per query (candidate split)

typedef unsigned long long u64;

__device__ float4 g_pred4[BATCH * NPTS];
__device__ float4 g_targ4[BATCH * NPTS];
__device__ float g_sx[2 * BATCH * NPTS];
__device__ float g_sy[2 * BATCH * NPTS];
__device__ float g_sz[2 * BATCH * NPTS];
__device__ float g_sw[2 * BATCH * NPTS];

__device__ __forceinline__ u64 pack2(float lo, float hi) {
    u64 r;
    asm("mov.b64 %0, {%1, %2};" : "=l"(r) : "f"(lo), "f"(hi));
    return r;
}
__device__ __forceinline__ float lo32(u64 v) { return __uint_as_float((unsigned)v); }
__device__ __forceinline__ float hi32(u64 v) { return __uint_as_float((unsigned)(v >> 32)); }
__device__ __forceinline__ u64 ffma2(u64 a, u64 b, u64 c) {
    u64 d;
    asm("fma.rn.f32x2 %0, %1, %2, %3;" : "=l"(d) : "l"(a), "l"(b), "l"(c));
    return d;
}

__global__ void prep_kernel(const float* __restrict__ src,
                            const float* __restrict__ tgt,
                            const float* __restrict__ flow) {
    int i = blockIdx.x * blockDim.x + threadIdx.x;
    if (i >= BATCH * NPTS) return;
    float px = src[3 * i + 0] + flow[3 * i + 0];
    float py = src[3 * i + 1] + flow[3 * i + 1];
    float pz = src[3 * i + 2] + flow[3 * i + 2];
    float pw = px * px + py * py + pz * pz;
    g_pred4[i] = make_float4(px, py, pz, pw);
    g_sx[i] = px; g_sy[i] = py; g_sz[i] = pz; g_sw[i] = pw;

    float tx = tgt[3 * i + 0], ty = tgt[3 * i + 1], tz = tgt[3 * i + 2];
    float tw = tx * tx + ty * ty + tz * tz;
    g_targ4[i] = make_float4(tx, ty, tz, tw);
    int j = BATCH * NPTS + i;
    g_sx[j] = tx; g_sy[j] = ty; g_sz[j] = tz; g_sw[j] = tw;
}

// Branchless sorted-descending insert (caller guarantees val < h[0])
#define INSERT8(h, val)                          \
    do {                                         \
        float _v = (val);                        \
        _Pragma("unroll")                        \
        for (int _i = 0; _i < KNN - 1; ++_i) {   \
            float _nx = h[_i + 1];               \
            h[_i] = fmaxf(_v, _nx);              \
            _v = fminf(_v, _nx);                 \
        }                                        \
        h[KNN - 1] = _v;                         \
    } while (0)

#define TRYINS(h, val) do { if ((val) < h[0]) INSERT8(h, (val)); } while (0)

__global__ void __launch_bounds__(THREADS, 8)
chamfer_kernel(float* __restrict__ out) {
    // Single shared buffer: x @ 0, y @ TILE, z @ 2*TILE, w @ 3*TILE
    __shared__ __align__(16) float sm[4 * TILE];
    __shared__ float m8[QBLK][KNN];
    __shared__ float red[QBLK];

    const int b   = blockIdx.y;
    const int dir = blockIdx.z;
    const float4* q4 = (dir == 0 ? g_pred4 : g_targ4) + b * NPTS;
    const int coff = (dir == 0 ? 1 : 0) * BATCH * NPTS + b * NPTS;

    const int qt   = threadIdx.x & (QBLK - 1);
    const int half = threadIdx.x >> 6;       // warp-uniform
    const int qi   = blockIdx.x * QBLK + qt;
    const float4 q = q4[qi];
    const u64 ax2 = pack2(-2.0f * q.x, -2.0f * q.x);
    const u64 ay2 = pack2(-2.0f * q.y, -2.0f * q.y);
    const u64 az2 = pack2(-2.0f * q.z, -2.0f * q.z);

    float h[KNN];
#pragma unroll
    for (int i = 0; i < KNN; ++i) h[i] = 1.0e30f;

    for (int t0 = 0; t0 < NPTS; t0 += TILE) {
        __syncthreads();
#pragma unroll
        for (int l = threadIdx.x; l < TILE / 4; l += THREADS) {
            ((float4*)sm)[l]                = ((const float4*)(g_sx + coff + t0))[l];
            ((float4*)(sm + TILE))[l]       = ((const float4*)(g_sy + coff + t0))[l];
            ((float4*)(sm + 2 * TILE))[l]   = ((const float4*)(g_sz + coff + t0))[l];
            ((float4*)(sm + 3 * TILE))[l]   = ((const float4*)(g_sw + coff + t0))[l];
        }
        __syncthreads();

        // Each thread handles interleaved 4-candidate groups (stride 8)
        const float* base = sm + 4 * half;
#pragma unroll 4
        for (int j = 0; j < TILE; j += 8) {
            const ulonglong2 X = *(const ulonglong2*)(base + j);
            const ulonglong2 Y = *(const ulonglong2*)(base + j + TILE);
            const ulonglong2 Z = *(const ulonglong2*)(base + j + 2 * TILE);
            const ulonglong2 W = *(const ulonglong2*)(base + j + 3 * TILE);

            // t = |c|^2 - 2 q.c  (ranking key; |q|^2 re-added at the end)
            u64 t01 = ffma2(ax2, X.x, ffma2(ay2, Y.x, ffma2(az2, Z.x, W.x)));
            u64 t23 = ffma2(ax2, X.y, ffma2(ay2, Y.y, ffma2(az2, Z.y, W.y)));

            float f0 = lo32(t01), f1 = hi32(t01);
            float f2 = lo32(t23), f3 = hi32(t23);

            float m = fminf(fminf(f0, f1), fminf(f2, f3));
            if (m < h[0]) {
                TRYINS(h, f0); TRYINS(h, f1);
                TRYINS(h, f2); TRYINS(h, f3);
            }
        }
    }

    // Merge the two halves' top-8 lists
    if (half) {
#pragma unroll
        for (int i = 0; i < KNN; ++i) m8[qt][i] = h[i];
    }
    __syncthreads();
    if (!half) {
#pragma unroll
        for (int i = 0; i < KNN; ++i)
            TRYINS(h, m8[qt][i]);
        float s = 0.0f;
#pragma unroll
        for (int i = 0; i < KNN; ++i)
            s += sqrtf(fmaxf(q.w + h[i], 0.0f));
        red[qt] = s;
    }
    __syncthreads();
#pragma unroll
    for (int off = QBLK / 2; off > 0; off >>= 1) {
        if (threadIdx.x < off) red[threadIdx.x] += red[threadIdx.x + off];
        __syncthreads();
    }
    if (threadIdx.x == 0)
        atomicAdd(out, red[0] * (1.0f / (KNN * BATCH * NPTS)));
}

extern "C" void kernel_launch(void* const* d_in, const int* in_sizes, int n_in,
                              void* d_out, int out_size) {
    const float* src  = (const float*)d_in[0];
    const float* tgt  = (const float*)d_in[1];
    const float* flow = (const float*)d_in[2];
    float* out = (float*)d_out;

    cudaMemsetAsync(out, 0, sizeof(float), 0);

    int npts = BATCH * NPTS;
    prep_kernel<<<(npts + 255) / 256, 256>>>(src, tgt, flow);

    dim3 grid(NPTS / QBLK, BATCH, 2);
    chamfer_kernel<<<grid, THREADS>>>(out);
}